// round 14
// baseline (speedup 1.0000x reference)
#include <cuda_runtime.h>
#include <cuda_fp16.h>
#include <math.h>
#include <stdint.h>

#define NB 32
#define WTOT 202112
#define SAMP 460800

__device__ float g_y[NB * WTOT];
__device__ float g_A[NB * 1048576];
__device__ float g_B[NB * 1048576];
__device__ float g_stats[NB * 64 * 2];
__device__ float g_part[262144];
__device__ __align__(16) unsigned char g_wimg[(size_t)NB * SAMP];

// ---------------- helpers ----------------
__device__ __forceinline__ uint16_t f2h(float v) {
    uint16_t r; asm("cvt.rn.f16.f32 %0, %1;" : "=h"(r) : "f"(v)); return r;
}
__device__ __forceinline__ uint32_t cvt2h(float hi, float lo) {
    uint32_t r; asm("cvt.rn.f16x2.f32 %0, %1, %2;" : "=r"(r) : "f"(hi), "f"(lo)); return r;
}
__device__ __forceinline__ void mma16816(float* c, uint32_t a0, uint32_t a1, uint32_t a2, uint32_t a3,
                                         uint32_t b0, uint32_t b1) {
    asm volatile("mma.sync.aligned.m16n8k16.row.col.f32.f16.f16.f32 "
        "{%0,%1,%2,%3}, {%4,%5,%6,%7}, {%8,%9}, {%0,%1,%2,%3};"
        : "+f"(c[0]), "+f"(c[1]), "+f"(c[2]), "+f"(c[3])
        : "r"(a0), "r"(a1), "r"(a2), "r"(a3), "r"(b0), "r"(b1));
}

// ---------------- merged weight generation ----------------
__global__ void gen_all(const float* __restrict__ W1, const float* __restrict__ B1,
                        const float* __restrict__ W2, const float* __restrict__ B2,
                        const float* __restrict__ W3, const float* __restrict__ B3,
                        const float* __restrict__ W4, const float* __restrict__ B4,
                        const float* __restrict__ W5, const float* __restrict__ B5,
                        const float* __restrict__ W6, const float* __restrict__ B6,
                        const float* __restrict__ W7, const float* __restrict__ B7,
                        const float* __restrict__ act) {
    __shared__ float sa[NB * 32];
    for (int i = threadIdx.x; i < NB * 32; i += blockDim.x) sa[i] = act[i];
    __syncthreads();
    int r = blockIdx.x * blockDim.x + threadIdx.x;
    if (r >= WTOT) return;
    const float* Wt; const float* bt; int local;
    if      (r < 3200)   { Wt = W1; bt = B1; local = r; }
    else if (r < 9600)   { Wt = W2; bt = B2; local = r - 3200; }
    else if (r < 22400)  { Wt = W3; bt = B3; local = r - 9600; }
    else if (r < 48000)  { Wt = W4; bt = B4; local = r - 22400; }
    else if (r < 99200)  { Wt = W5; bt = B5; local = r - 48000; }
    else if (r < 201600) { Wt = W6; bt = B6; local = r - 99200; }
    else                 { Wt = W7; bt = B7; local = r - 201600; }
    float w[32];
    const float4* wp = reinterpret_cast<const float4*>(Wt + (size_t)local * 32);
#pragma unroll
    for (int i = 0; i < 8; i++) { float4 v = wp[i]; w[4*i]=v.x; w[4*i+1]=v.y; w[4*i+2]=v.z; w[4*i+3]=v.w; }
    float bv = bt[local];
    for (int s = 0; s < NB; s++) {
        float acc = bv;
#pragma unroll
        for (int k = 0; k < 32; k++) acc = fmaf(w[k], sa[s*32+k], acc);
        g_y[(size_t)s * WTOT + r] = acc;
    }
}

// ---------------- weight image prep (fragment-contiguous layout) -----------
// Layers 2-6: per chunk, addr = ((((tap*8+g)*4+t)*NN + n)*2 + j) u32, fp16 half = cc&1.
// (g = cout&7, n = cout>>3, t = (cc&7)>>1, j = cc>>3)
// conv1 (tap-paired): q in 0..12, k = tap-pair index; same fragment mapping with NN=2.
__global__ void prep_all() {
    int e = blockIdx.x * 256 + threadIdx.x;
    int b = blockIdx.y;
    if (e >= 201728) return;
    if (e >= 198400) {                       // conv1 image @ 396800
        e -= 198400;                          // 13 * 256
        int q = e >> 8, rem = e & 255;
        int cout = rem >> 4, kk = rem & 15;
        int tap = 2 * q + (kk >> 3);
        float v = 0.f;
        if (tap < 25)
            v = g_y[(size_t)b * WTOT + ((size_t)cout * 8 + (kk & 7)) * 25 + tap];
        int g = cout & 7, n = cout >> 3;
        int t = (kk & 7) >> 1, j = kk >> 3, half = kk & 1;
        size_t addr = (size_t)b * SAMP + 396800
                    + (size_t)(((((q*8+g)*4+t)*2 + n)*2 + j)*4 + half*2);
        *(uint16_t*)(g_wimg + addr) = f2h(v);
        return;
    }
    int wOff, Cout, CinReal, imgOff, WBn;
    if      (e < 12800)  { wOff=9600;  Cout=32; CinReal=16; imgOff=0;      WBn=25600; }
    else if (e < 38400)  { wOff=22400; Cout=32; CinReal=32; imgOff=25600;  WBn=25600; e-=12800; }
    else if (e < 89600)  { wOff=48000; Cout=64; CinReal=32; imgOff=76800;  WBn=51200; e-=38400; }
    else if (e < 192000) { wOff=99200; Cout=64; CinReal=64; imgOff=179200; WBn=51200; e-=89600; }
    else                 { wOff=3200;  Cout=16; CinReal=16; imgOff=384000; WBn=12800; e-=192000; }
    int per = 25 * Cout * 16;
    int chunk = e / per; int rem = e - chunk * per;
    int tap = rem / (Cout * 16); int rem2 = rem - tap * (Cout * 16);
    int cout = rem2 >> 4, cc = rem2 & 15;
    float v = g_y[(size_t)b * WTOT + wOff + ((size_t)cout * CinReal + chunk * 16 + cc) * 25 + tap];
    int NN = Cout >> 3;
    int g = cout & 7, n = cout >> 3;
    int t = (cc & 7) >> 1, j = cc >> 3, half = cc & 1;
    size_t addr = (size_t)b * SAMP + imgOff + (size_t)chunk * WBn
                + (size_t)(((((tap*8+g)*4+t)*NN + n)*2 + j)*4 + half*2);
    *(uint16_t*)(g_wimg + addr) = f2h(v);
}

// ---------------- BN stats (layer 0 on x only) ----------------
__global__ void bn_stats(const float* __restrict__ src, const float* __restrict__ g,
                         const float* __restrict__ be, int C, int HW) {
    int plane = blockIdx.x;
    int c = plane % C;
    const float* p = src + (size_t)plane * HW;
    float s = 0.f, s2 = 0.f;
    for (int i = threadIdx.x; i < HW; i += 256) { float v = p[i]; s += v; s2 = fmaf(v, v, s2); }
    __shared__ float sh0[256], sh1[256];
    sh0[threadIdx.x] = s; sh1[threadIdx.x] = s2;
    __syncthreads();
    for (int ofs = 128; ofs > 0; ofs >>= 1) {
        if (threadIdx.x < ofs) { sh0[threadIdx.x] += sh0[threadIdx.x+ofs]; sh1[threadIdx.x] += sh1[threadIdx.x+ofs]; }
        __syncthreads();
    }
    if (threadIdx.x == 0) {
        float inv = 1.f / (float)HW;
        float m = sh0[0] * inv;
        float var = sh1[0] * inv - m * m;
        float sc = g[c] * rsqrtf(var + 1e-5f);
        g_stats[plane*2] = sc;
        g_stats[plane*2+1] = be[c] - m * sc;
    }
}

// ---------------- BN finalize (deterministic fixed-order tile sum) ---------
__global__ void bn_finalize(const float* __restrict__ gamma, const float* __restrict__ beta,
                            int C, int NT, float invHW) {
    int idx = blockIdx.x * 256 + threadIdx.x;
    if (idx >= NB * C) return;
    int b = idx / C, c = idx - b * C;
    float s = 0.f, q = 0.f;
    for (int tIdx = 0; tIdx < NT; tIdx++) {
        const float* p = g_part + (((size_t)b * NT + tIdx) * C + c) * 2;
        s += p[0]; q += p[1];
    }
    float m = s * invHW;
    float var = q * invHW - m * m;
    float sc = gamma[c] * rsqrtf(var + 1e-5f);
    g_stats[idx*2]   = sc;
    g_stats[idx*2+1] = beta[c] - m * sc;
}

// ---------------- stats epilogue ----------------
template<int T, int NN, int COUT>
__device__ __forceinline__ void stats_epilogue(float (*acc)[NN][4], char* dsm,
                                               int tid, int w, int lane, int t,
                                               int b, int tile, int nt) {
    float st[NN][4];
#pragma unroll
    for (int n = 0; n < NN; n++) {
        float s0=0.f,q0=0.f,s1=0.f,q1=0.f;
#pragma unroll
        for (int i = 0; i < T; i++) {
            float a0=acc[i][n][0], a1=acc[i][n][1], a2=acc[i][n][2], a3=acc[i][n][3];
            s0 += a0 + a2; q0 = fmaf(a0,a0,fmaf(a2,a2,q0));
            s1 += a1 + a3; q1 = fmaf(a1,a1,fmaf(a3,a3,q1));
        }
        st[n][0]=s0; st[n][1]=q0; st[n][2]=s1; st[n][3]=q1;
    }
#pragma unroll
    for (int n = 0; n < NN; n++)
#pragma unroll
        for (int j = 0; j < 4; j++) {
            st[n][j] += __shfl_xor_sync(0xffffffffu, st[n][j], 4);
            st[n][j] += __shfl_xor_sync(0xffffffffu, st[n][j], 8);
            st[n][j] += __shfl_xor_sync(0xffffffffu, st[n][j], 16);
        }
    float* sred = (float*)dsm;
    __syncthreads();
    if (lane < 4) {
#pragma unroll
        for (int n = 0; n < NN; n++)
#pragma unroll
            for (int j = 0; j < 4; j++)
                sred[((w * NN + n) * 4 + t) * 4 + j] = st[n][j];
    }
    __syncthreads();
    if (tid < NN * 16) {
        int n = tid >> 4, tt = (tid >> 2) & 3, j = tid & 3;
        float s = 0.f;
#pragma unroll
        for (int ww = 0; ww < 8; ww++) s += sred[((ww * NN + n) * 4 + tt) * 4 + j];
        int c = n * 8 + 2 * tt + (j >> 1);
        g_part[(((size_t)b * nt + tile) * COUT + c) * 2 + (j & 1)] = s;
    }
}

// ---------------- mma.sync conv (convs 2-6): stage-only smem, gmem B -------
template<int DIL, int MODE, int CIN, int CREAL, int COUT, int S, int XTILE, int POOL, int MINB>
__global__ __launch_bounds__(256, MINB)
void conv_mma(const float* __restrict__ in, float* __restrict__ out, int imgOff) {
    constexpr int WBn = COUT * 800;          // bytes per chunk image
    constexpr int NC = CIN / 16;
    constexpr int XP = XTILE + 4 * DIL;
    constexpr int R  = 4 + 4 * DIL;
    constexpr int PS0 = R * XP;
    constexpr int PSTRIDE = PS0 + ((40 - (PS0 & 31)) & 31);
    constexpr int T  = XTILE / 32;
    constexpr int NN = COUT / 8;
    constexpr int NXT = S / XTILE;
    extern __shared__ __align__(16) char dsm[];
    uint32_t* sStage = (uint32_t*)dsm;
    const int tid = threadIdx.x, w = tid >> 5, lane = tid & 31;
    const int g = lane >> 2, t = lane & 3;
    const int b = blockIdx.y;
    const int xt = blockIdx.x % NXT, yt = blockIdx.x / NXT;
    const int y0 = yt * 4, x0 = xt * XTILE;
    const int ry = w >> 1, xseg = (w & 1) * (XTILE / 2);
    float acc[T][NN][4];
#pragma unroll
    for (int i = 0; i < T; i++)
#pragma unroll
        for (int n = 0; n < NN; n++)
#pragma unroll
            for (int j = 0; j < 4; j++) acc[i][n][j] = 0.f;
    const unsigned char* img = g_wimg + (size_t)b * SAMP + imgOff;

#pragma unroll 1
    for (int chunk = 0; chunk < NC; chunk++) {
        __syncthreads();
        {   // stage 16 channels as f16x2 pairs (hi p0-7, lo p8-15), BN folded
            int cb = chunk * 16;
            for (int idx = tid; idx < 8 * PS0; idx += 256) {
                int p = idx / PS0, rem = idx - p * PS0;
                int r = rem / XP, xp = rem - r * XP;
                int iy = y0 + r - 2 * DIL, ix = x0 + xp - 2 * DIL;
                int c0 = cb + p * 2;
                float v0 = 0.f, v1 = 0.f;
                if (iy >= 0 && iy < S && ix >= 0 && ix < S && c0 < CREAL) {
                    const float* bp = in + ((size_t)(b * CREAL + c0)) * (S * S) + (size_t)iy * S + ix;
                    v0 = bp[0]; v1 = bp[(size_t)S * S];
                    if (MODE) {
                        v0 = fmaf(v0, g_stats[(b*CREAL+c0)*2],   g_stats[(b*CREAL+c0)*2+1]);
                        v1 = fmaf(v1, g_stats[(b*CREAL+c0+1)*2], g_stats[(b*CREAL+c0+1)*2+1]);
                        if (MODE == 2) { v0 = fmaxf(v0, 0.f); v1 = fmaxf(v1, 0.f); }
                    }
                }
                uint32_t hp = cvt2h(v1, v0);
                __half2 hh = *reinterpret_cast<__half2*>(&hp);
                float2 bk = __half22float2(hh);
                uint32_t lp = cvt2h(v1 - bk.y, v0 - bk.x);
                sStage[p * PSTRIDE + rem]       = hp;
                sStage[(8 + p) * PSTRIDE + rem] = lp;
            }
        }
        __syncthreads();
        const unsigned char* imgC = img + (size_t)chunk * WBn;
#pragma unroll 1
        for (int ky = 0; ky < 5; ky++) {
#pragma unroll 1
            for (int kx = 0; kx < 5; kx++) {
                int off = (ry + ky * DIL) * XP + xseg + kx * DIL + g;
                uint32_t ah[T][4], al[T][4];
#pragma unroll
                for (int i = 0; i < T; i++) {
                    int o = off + i * 16;
                    ah[i][0] = sStage[t * PSTRIDE + o];
                    ah[i][1] = sStage[t * PSTRIDE + o + 8];
                    ah[i][2] = sStage[(t + 4) * PSTRIDE + o];
                    ah[i][3] = sStage[(t + 4) * PSTRIDE + o + 8];
                    al[i][0] = sStage[(t + 8) * PSTRIDE + o];
                    al[i][1] = sStage[(t + 8) * PSTRIDE + o + 8];
                    al[i][2] = sStage[(t + 12) * PSTRIDE + o];
                    al[i][3] = sStage[(t + 12) * PSTRIDE + o + 8];
                }
                // B fragments straight from gmem (L1-resident, uniform addr)
                const uint4* wp = (const uint4*)(imgC + (size_t)((((ky*5+kx)*8 + g)*4 + t) * (NN * 8)));
                uint32_t bb[NN][2];
#pragma unroll
                for (int nn = 0; nn < NN / 2; nn++) {
                    uint4 qv = wp[nn];
                    bb[2*nn][0] = qv.x; bb[2*nn][1] = qv.y;
                    bb[2*nn+1][0] = qv.z; bb[2*nn+1][1] = qv.w;
                }
#pragma unroll
                for (int n = 0; n < NN; n++)
#pragma unroll
                    for (int i = 0; i < T; i++)
                        mma16816(acc[i][n], ah[i][0], ah[i][1], ah[i][2], ah[i][3], bb[n][0], bb[n][1]);
#pragma unroll
                for (int n = 0; n < NN; n++)
#pragma unroll
                    for (int i = 0; i < T; i++)
                        mma16816(acc[i][n], al[i][0], al[i][1], al[i][2], al[i][3], bb[n][0], bb[n][1]);
            }
        }
    }
    if (!POOL) {
        int row = y0 + ry;
        float* orow = out + ((size_t)b * COUT) * (S * S) + (size_t)row * S;
#pragma unroll
        for (int i = 0; i < T; i++) {
            int px = x0 + xseg + i * 16 + g;
#pragma unroll
            for (int n = 0; n < NN; n++) {
                float* p0 = orow + ((size_t)(n * 8 + 2 * t)) * (S * S);
                float* p1 = p0 + (size_t)S * S;
                p0[px]     = acc[i][n][0];
                p1[px]     = acc[i][n][1];
                p0[px + 8] = acc[i][n][2];
                p1[px + 8] = acc[i][n][3];
            }
        }
    }
    stats_epilogue<T, NN, COUT>(acc, dsm, tid, w, lane, t, b, blockIdx.x, gridDim.x);
    if (POOL) {
        float* pbuf = (float*)(dsm + 4096);
#pragma unroll
        for (int i = 0; i < T; i++) {
            int col = xseg + i * 16 + g;
#pragma unroll
            for (int n = 0; n < NN; n++) {
                int c0 = n * 8 + 2 * t;
                pbuf[c0 * (4 * XTILE) + ry * XTILE + col]           = acc[i][n][0];
                pbuf[(c0 + 1) * (4 * XTILE) + ry * XTILE + col]     = acc[i][n][1];
                pbuf[c0 * (4 * XTILE) + ry * XTILE + col + 8]       = acc[i][n][2];
                pbuf[(c0 + 1) * (4 * XTILE) + ry * XTILE + col + 8] = acc[i][n][3];
            }
        }
        __syncthreads();
        for (int k = tid; k < COUT * 2 * (XTILE / 2); k += 256) {
            int c = k / (2 * (XTILE / 2));
            int rem = k - c * 2 * (XTILE / 2);
            int pr = rem / (XTILE / 2), pc = rem - pr * (XTILE / 2);
            const float* pb = pbuf + c * (4 * XTILE);
            float v = 0.25f * (pb[(2*pr) * XTILE + 2*pc] + pb[(2*pr) * XTILE + 2*pc + 1]
                             + pb[(2*pr+1) * XTILE + 2*pc] + pb[(2*pr+1) * XTILE + 2*pc + 1]);
            out[((size_t)(b * COUT + c)) * ((S/2)*(S/2)) + (size_t)(y0/2 + pr) * (S/2) + (x0/2 + pc)] = v;
        }
    }
}

// ---------------- conv1: tap-paired k16, gmem B ----------------------------
__global__ __launch_bounds__(256)
void conv1_mma(const float* __restrict__ in, float* __restrict__ out, int imgOff) {
    constexpr int S = 256, XTILE = 128, XP = 136, PS0 = 12 * 136;
    constexpr int PSTRIDE = 1640, T = 4, NN = 2;
    extern __shared__ __align__(16) char dsm[];
    uint32_t* sStage = (uint32_t*)dsm;
    const int tid = threadIdx.x, w = tid >> 5, lane = tid & 31;
    const int g = lane >> 2, t = lane & 3;
    const int b = blockIdx.y;
    const int xt = blockIdx.x & 1, yt = blockIdx.x >> 1;
    const int y0 = yt * 4, x0 = xt * XTILE;
    const int ry = w >> 1, xseg = (w & 1) * 64;
    float acc[T][NN][4];
#pragma unroll
    for (int i = 0; i < T; i++)
#pragma unroll
        for (int n = 0; n < NN; n++)
#pragma unroll
            for (int j = 0; j < 4; j++) acc[i][n][j] = 0.f;
    const unsigned char* img = g_wimg + (size_t)b * SAMP + imgOff;
    {
        for (int idx = tid; idx < 4 * PS0; idx += 256) {
            int p = idx / PS0, rem = idx - p * PS0;
            int r = rem / XP, xp = rem - r * XP;
            int iy = y0 + r - 4, ix = x0 + xp - 4;
            int c0 = p * 2;
            float v0 = 0.f, v1 = 0.f;
            if (iy >= 0 && iy < S && ix >= 0 && ix < S) {
                const float* bp = in + ((size_t)(b * 8 + c0)) * 65536 + (size_t)iy * S + ix;
                v0 = bp[0]; v1 = bp[65536];
                v0 = fmaf(v0, g_stats[(b*8+c0)*2],   g_stats[(b*8+c0)*2+1]);
                v1 = fmaf(v1, g_stats[(b*8+c0+1)*2], g_stats[(b*8+c0+1)*2+1]);
            }
            uint32_t hp = cvt2h(v1, v0);
            __half2 hh = *reinterpret_cast<__half2*>(&hp);
            float2 bk = __half22float2(hh);
            uint32_t lp = cvt2h(v1 - bk.y, v0 - bk.x);
            sStage[p * PSTRIDE + rem]       = hp;
            sStage[(4 + p) * PSTRIDE + rem] = lp;
        }
    }
    __syncthreads();
#pragma unroll 1
    for (int q = 0; q < 13; q++) {
        int tap1 = 2 * q, tap2 = (2 * q + 1 < 25) ? 2 * q + 1 : 24;
        int ky1 = tap1 / 5, kx1 = tap1 - ky1 * 5;
        int ky2 = tap2 / 5, kx2 = tap2 - ky2 * 5;
        int o1 = (ry + ky1 * 2) * XP + xseg + kx1 * 2 + g;
        int o2 = (ry + ky2 * 2) * XP + xseg + kx2 * 2 + g;
        uint32_t ah[T][4], al[T][4];
#pragma unroll
        for (int i = 0; i < T; i++) {
            int p1 = o1 + i * 16, p2 = o2 + i * 16;
            ah[i][0] = sStage[t * PSTRIDE + p1];
            ah[i][1] = sStage[t * PSTRIDE + p1 + 8];
            ah[i][2] = sStage[t * PSTRIDE + p2];
            ah[i][3] = sStage[t * PSTRIDE + p2 + 8];
            al[i][0] = sStage[(t + 4) * PSTRIDE + p1];
            al[i][1] = sStage[(t + 4) * PSTRIDE + p1 + 8];
            al[i][2] = sStage[(t + 4) * PSTRIDE + p2];
            al[i][3] = sStage[(t + 4) * PSTRIDE + p2 + 8];
        }
        const uint4* wp = (const uint4*)(img + (size_t)(((q*8+g)*4+t) * 16));
        uint4 qv = *wp;
        uint32_t bb[NN][2];
        bb[0][0] = qv.x; bb[0][1] = qv.y; bb[1][0] = qv.z; bb[1][1] = qv.w;
#pragma unroll
        for (int n = 0; n < NN; n++)
#pragma unroll
            for (int i = 0; i < T; i++)
                mma16816(acc[i][n], ah[i][0], ah[i][1], ah[i][2], ah[i][3], bb[n][0], bb[n][1]);
#pragma unroll
        for (int n = 0; n < NN; n++)
#pragma unroll
            for (int i = 0; i < T; i++)
                mma16816(acc[i][n], al[i][0], al[i][1], al[i][2], al[i][3], bb[n][0], bb[n][1]);
    }
    int row = y0 + ry;
    float* orow = out + ((size_t)b * 16) * 65536 + (size_t)row * S;
#pragma unroll
    for (int i = 0; i < T; i++) {
        int px = x0 + xseg + i * 16 + g;
#pragma unroll
        for (int n = 0; n < NN; n++) {
            float* p0 = orow + ((size_t)(n * 8 + 2 * t)) * 65536;
            float* p1 = p0 + 65536;
            p0[px]     = acc[i][n][0];
            p1[px]     = acc[i][n][1];
            p0[px + 8] = acc[i][n][2];
            p1[px + 8] = acc[i][n][3];
        }
    }
    stats_epilogue<T, NN, 16>(acc, dsm, tid, w, lane, t, b, blockIdx.x, gridDim.x);
}

// ---------------- 1x1 conv / upsample+softmax ----------------
__global__ void conv1x1(const float* __restrict__ in, float* __restrict__ out) {
    __shared__ float sw[512];
    int b = blockIdx.y;
    const float* wb = g_y + (size_t)b * WTOT + 201600;
    for (int i = threadIdx.x; i < 512; i += blockDim.x) sw[i] = wb[i];
    __syncthreads();
    int pix = blockIdx.x * blockDim.x + threadIdx.x;
    if (pix >= 16384) return;
    float acc[8] = {0,0,0,0,0,0,0,0};
    for (int c = 0; c < 64; c++) {
        float v = in[((size_t)(b*64 + c)) * 16384 + pix];
        v = fmaf(v, g_stats[(b*64+c)*2], g_stats[(b*64+c)*2+1]);
#pragma unroll
        for (int o = 0; o < 8; o++) acc[o] = fmaf(v, sw[o*64 + c], acc[o]);
    }
#pragma unroll
    for (int o = 0; o < 8; o++) out[((size_t)(b*8 + o)) * 16384 + pix] = acc[o];
}

__global__ void up_softmax(const float* __restrict__ in, float* __restrict__ out) {
    int idx = blockIdx.x * blockDim.x + threadIdx.x;
    if (idx >= NB * 65536) return;
    int x = idx & 255, y = (idx >> 8) & 255, b = idx >> 16;
    const float r = 127.0f / 255.0f;
    float sy = y * r, sx = x * r;
    int y0 = (int)sy, x0 = (int)sx;
    int y1 = min(y0 + 1, 127), x1 = min(x0 + 1, 127);
    float wy = sy - (float)y0, wx = sx - (float)x0;
    const float* bp = in + (size_t)b * 8 * 16384;
    float v[8], m = -1e30f;
#pragma unroll
    for (int o = 0; o < 8; o++) {
        const float* p = bp + o * 16384;
        float a00 = p[y0*128+x0], a01 = p[y0*128+x1];
        float a10 = p[y1*128+x0], a11 = p[y1*128+x1];
        float t0 = a00 * (1.f - wy) + a10 * wy;
        float t1 = a01 * (1.f - wy) + a11 * wy;
        v[o] = t0 * (1.f - wx) + t1 * wx;
        m = fmaxf(m, v[o]);
    }
    float s = 0.f;
#pragma unroll
    for (int o = 0; o < 8; o++) { v[o] = expf(v[o] - m); s += v[o]; }
    float invs = 1.f / s;
    size_t base = ((size_t)b * 8) * 65536 + (size_t)y * 256 + x;
#pragma unroll
    for (int o = 0; o < 8; o++) out[base + (size_t)o * 65536] = v[o] * invs;
}

// ---------------------------------------------------------------------------
extern "C" void kernel_launch(void* const* d_in, const int* in_sizes, int n_in,
                              void* d_out, int out_size) {
    const float* x   = (const float*)d_in[0];
    const float* act = (const float*)d_in[1];
    const float* g[7]; const float* be[7];
    for (int i = 0; i < 7; i++) { g[i] = (const float*)d_in[16 + 2*i]; be[i] = (const float*)d_in[17 + 2*i]; }
    float* out = (float*)d_out;
    float *pA = nullptr, *pB = nullptr;
    cudaGetSymbolAddress((void**)&pA, g_A);
    cudaGetSymbolAddress((void**)&pB, g_B);

    // stage-only smem
    const int SM1 = 8  * 1640 * 4;   // 52480 -> 4 CTAs
    const int SM2 = 16 * 1064 * 4;   // 68096 -> 3
    const int SM3 = 16 * 872  * 4;   // 55808
    const int SM4 = 16 * 552  * 4;   // 35328
    const int SM5 = 16 * 872  * 4;   // 55808
    const int SM6 = 16 * 552  * 4;   // 35328
    cudaFuncSetAttribute(conv1_mma, cudaFuncAttributeMaxDynamicSharedMemorySize, SM1);
    cudaFuncSetAttribute(conv_mma<1,2,16,16,16,256,128,1,3>, cudaFuncAttributeMaxDynamicSharedMemorySize, SM2);
    cudaFuncSetAttribute(conv_mma<2,1,16,16,32,128,64,0,3>,  cudaFuncAttributeMaxDynamicSharedMemorySize, SM3);
    cudaFuncSetAttribute(conv_mma<1,2,32,32,32,128,64,0,3>,  cudaFuncAttributeMaxDynamicSharedMemorySize, SM4);
    cudaFuncSetAttribute(conv_mma<2,1,32,32,64,128,64,0,2>,  cudaFuncAttributeMaxDynamicSharedMemorySize, SM5);
    cudaFuncSetAttribute(conv_mma<1,2,64,64,64,128,64,0,2>,  cudaFuncAttributeMaxDynamicSharedMemorySize, SM6);

    gen_all<<<(WTOT + 255) / 256, 256>>>(
        (const float*)d_in[2],  (const float*)d_in[3],
        (const float*)d_in[4],  (const float*)d_in[5],
        (const float*)d_in[6],  (const float*)d_in[7],
        (const float*)d_in[8],  (const float*)d_in[9],
        (const float*)d_in[10], (const float*)d_in[11],
        (const float*)d_in[12], (const float*)d_in[13],
        (const float*)d_in[14], (const float*)d_in[15], act);
    prep_all<<<dim3((201728 + 255) / 256, NB), 256>>>();

    bn_stats<<<NB * 8, 256>>>(x, g[0], be[0], 8, 65536);
    conv1_mma<<<dim3(128, NB), 256, SM1>>>(x, pA, 396800);
    bn_finalize<<<(NB*16 + 255)/256, 256>>>(g[1], be[1], 16, 128, 1.f/65536.f);
    conv_mma<1,2,16,16,16,256,128,1,3><<<dim3(128, NB), 256, SM2>>>(pA, pB, 384000);  // conv2 + pool
    bn_finalize<<<(NB*16 + 255)/256, 256>>>(g[2], be[2], 16, 128, 1.f/65536.f);
    conv_mma<2,1,16,16,32,128,64,0,3><<<dim3(64, NB), 256, SM3>>>(pB, pA, 0);         // conv3
    bn_finalize<<<(NB*32 + 255)/256, 256>>>(g[3], be[3], 32, 64, 1.f/16384.f);
    conv_mma<1,2,32,32,32,128,64,0,3><<<dim3(64, NB), 256, SM4>>>(pA, pB, 25600);     // conv4
    bn_finalize<<<(NB*32 + 255)/256, 256>>>(g[4], be[4], 32, 64, 1.f/16384.f);
    conv_mma<2,1,32,32,64,128,64,0,2><<<dim3(64, NB), 256, SM5>>>(pB, pA, 76800);     // conv5
    bn_finalize<<<(NB*64 + 255)/256, 256>>>(g[5], be[5], 64, 64, 1.f/16384.f);
    conv_mma<1,2,64,64,64,128,64,0,2><<<dim3(64, NB), 256, SM6>>>(pA, pB, 179200);    // conv6
    bn_finalize<<<(NB*64 + 255)/256, 256>>>(g[6], be[6], 64, 64, 1.f/16384.f);

    conv1x1<<<dim3(64, NB), 256>>>(pB, pA);
    up_softmax<<<(NB * 65536 + 255) / 256, 256>>>(pA, out);
}

// round 15
// speedup vs baseline: 1.0773x; 1.0773x over previous
#include <cuda_runtime.h>
#include <cuda_fp16.h>
#include <math.h>
#include <stdint.h>

#define NB 32
#define WTOT 202112
#define SAMP 460800

__device__ float g_y[NB * WTOT];
__device__ float g_A[NB * 1048576];
__device__ float g_B[NB * 1048576];
__device__ float g_stats[NB * 64 * 2];
__device__ float g_part[262144];
__device__ __align__(16) unsigned char g_wimg[(size_t)NB * SAMP];

// ---------------- helpers ----------------
__device__ __forceinline__ uint16_t f2h(float v) {
    uint16_t r; asm("cvt.rn.f16.f32 %0, %1;" : "=h"(r) : "f"(v)); return r;
}
__device__ __forceinline__ uint32_t cvt2h(float hi, float lo) {
    uint32_t r; asm("cvt.rn.f16x2.f32 %0, %1, %2;" : "=r"(r) : "f"(hi), "f"(lo)); return r;
}
__device__ __forceinline__ void mma16816(float* c, uint32_t a0, uint32_t a1, uint32_t a2, uint32_t a3,
                                         uint32_t b0, uint32_t b1) {
    asm volatile("mma.sync.aligned.m16n8k16.row.col.f32.f16.f16.f32 "
        "{%0,%1,%2,%3}, {%4,%5,%6,%7}, {%8,%9}, {%0,%1,%2,%3};"
        : "+f"(c[0]), "+f"(c[1]), "+f"(c[2]), "+f"(c[3])
        : "r"(a0), "r"(a1), "r"(a2), "r"(a3), "r"(b0), "r"(b1));
}

// ---------------- merged weight generation ----------------
__global__ void gen_all(const float* __restrict__ W1, const float* __restrict__ B1,
                        const float* __restrict__ W2, const float* __restrict__ B2,
                        const float* __restrict__ W3, const float* __restrict__ B3,
                        const float* __restrict__ W4, const float* __restrict__ B4,
                        const float* __restrict__ W5, const float* __restrict__ B5,
                        const float* __restrict__ W6, const float* __restrict__ B6,
                        const float* __restrict__ W7, const float* __restrict__ B7,
                        const float* __restrict__ act) {
    __shared__ float sa[NB * 32];
    for (int i = threadIdx.x; i < NB * 32; i += blockDim.x) sa[i] = act[i];
    __syncthreads();
    int r = blockIdx.x * blockDim.x + threadIdx.x;
    if (r >= WTOT) return;
    const float* Wt; const float* bt; int local;
    if      (r < 3200)   { Wt = W1; bt = B1; local = r; }
    else if (r < 9600)   { Wt = W2; bt = B2; local = r - 3200; }
    else if (r < 22400)  { Wt = W3; bt = B3; local = r - 9600; }
    else if (r < 48000)  { Wt = W4; bt = B4; local = r - 22400; }
    else if (r < 99200)  { Wt = W5; bt = B5; local = r - 48000; }
    else if (r < 201600) { Wt = W6; bt = B6; local = r - 99200; }
    else                 { Wt = W7; bt = B7; local = r - 201600; }
    float w[32];
    const float4* wp = reinterpret_cast<const float4*>(Wt + (size_t)local * 32);
#pragma unroll
    for (int i = 0; i < 8; i++) { float4 v = wp[i]; w[4*i]=v.x; w[4*i+1]=v.y; w[4*i+2]=v.z; w[4*i+3]=v.w; }
    float bv = bt[local];
    for (int s = 0; s < NB; s++) {
        float acc = bv;
#pragma unroll
        for (int k = 0; k < 32; k++) acc = fmaf(w[k], sa[s*32+k], acc);
        g_y[(size_t)s * WTOT + r] = acc;
    }
}

// ---------------- weight image prep ----------------------------------------
// Layers 2-6: [chunk][tap][cout][18ch] fp16 (smem-copy path).
// conv1: fragment-contiguous gmem-B path (tap-paired k16, NN=2).
__global__ void prep_all() {
    int e = blockIdx.x * 256 + threadIdx.x;
    int b = blockIdx.y;
    if (e >= 226528) return;
    if (e >= 223200) {                       // conv1 fragment image @ 446400
        e -= 223200;                         // 13 * 256 = 3328
        int q = e >> 8, rem = e & 255;
        int cout = rem >> 4, kk = rem & 15;
        int tap = 2 * q + (kk >> 3);
        float v = 0.f;
        if (tap < 25)
            v = g_y[(size_t)b * WTOT + ((size_t)cout * 8 + (kk & 7)) * 25 + tap];
        int g = cout & 7, n = cout >> 3;
        int t = (kk & 7) >> 1, j = kk >> 3, half = kk & 1;
        size_t addr = (size_t)b * SAMP + 446400
                    + (size_t)(((((q*8+g)*4+t)*2 + n)*2 + j)*4 + half*2);
        *(uint16_t*)(g_wimg + addr) = f2h(v);
        return;
    }
    int wOff, Cout, CinReal, imgOff;
    if      (e < 14400)  { wOff = 9600;   Cout = 32; CinReal = 16; imgOff = 0;      }
    else if (e < 43200)  { wOff = 22400;  Cout = 32; CinReal = 32; imgOff = 28800;  e -= 14400; }
    else if (e < 100800) { wOff = 48000;  Cout = 64; CinReal = 32; imgOff = 86400;  e -= 43200; }
    else if (e < 216000) { wOff = 99200;  Cout = 64; CinReal = 64; imgOff = 201600; e -= 100800; }
    else                 { wOff = 3200;   Cout = 16; CinReal = 16; imgOff = 432000; e -= 216000; }
    int per = 25 * Cout * 18;
    int chunk = e / per; int rem = e - chunk * per;
    int tap = rem / (Cout * 18); int rem2 = rem - tap * Cout * 18;
    int cout = rem2 / 18; int cc = rem2 - cout * 18;
    int cin = chunk * 16 + cc;
    float v = 0.f;
    if (cc < 16 && cin < CinReal)
        v = g_y[(size_t)b * WTOT + wOff + ((size_t)cout * CinReal + cin) * 25 + tap];
    size_t base = (size_t)b * SAMP + imgOff + (size_t)chunk * (25 * Cout * 36)
                + ((size_t)(tap * Cout + cout) * 18 + cc) * 2;
    *(uint16_t*)(g_wimg + base) = f2h(v);
}

// ---------------- BN stats (layer 0 on x only) ----------------
__global__ void bn_stats(const float* __restrict__ src, const float* __restrict__ g,
                         const float* __restrict__ be, int C, int HW) {
    int plane = blockIdx.x;
    int c = plane % C;
    const float* p = src + (size_t)plane * HW;
    float s = 0.f, s2 = 0.f;
    for (int i = threadIdx.x; i < HW; i += 256) { float v = p[i]; s += v; s2 = fmaf(v, v, s2); }
    __shared__ float sh0[256], sh1[256];
    sh0[threadIdx.x] = s; sh1[threadIdx.x] = s2;
    __syncthreads();
    for (int ofs = 128; ofs > 0; ofs >>= 1) {
        if (threadIdx.x < ofs) { sh0[threadIdx.x] += sh0[threadIdx.x+ofs]; sh1[threadIdx.x] += sh1[threadIdx.x+ofs]; }
        __syncthreads();
    }
    if (threadIdx.x == 0) {
        float inv = 1.f / (float)HW;
        float m = sh0[0] * inv;
        float var = sh1[0] * inv - m * m;
        float sc = g[c] * rsqrtf(var + 1e-5f);
        g_stats[plane*2] = sc;
        g_stats[plane*2+1] = be[c] - m * sc;
    }
}

// ---------------- BN finalize (deterministic fixed-order tile sum) ---------
__global__ void bn_finalize(const float* __restrict__ gamma, const float* __restrict__ beta,
                            int C, int NT, float invHW) {
    int idx = blockIdx.x * 256 + threadIdx.x;
    if (idx >= NB * C) return;
    int b = idx / C, c = idx - b * C;
    float s = 0.f, q = 0.f;
    for (int tIdx = 0; tIdx < NT; tIdx++) {
        const float* p = g_part + (((size_t)b * NT + tIdx) * C + c) * 2;
        s += p[0]; q += p[1];
    }
    float m = s * invHW;
    float var = q * invHW - m * m;
    float sc = gamma[c] * rsqrtf(var + 1e-5f);
    g_stats[idx*2]   = sc;
    g_stats[idx*2+1] = beta[c] - m * sc;
}

// ---------------- stats epilogue ----------------
template<int T, int NN, int COUT>
__device__ __forceinline__ void stats_epilogue(float (*acc)[NN][4], char* dsm,
                                               int tid, int w, int lane, int t,
                                               int b, int tile, int nt) {
    float st[NN][4];
#pragma unroll
    for (int n = 0; n < NN; n++) {
        float s0=0.f,q0=0.f,s1=0.f,q1=0.f;
#pragma unroll
        for (int i = 0; i < T; i++) {
            float a0=acc[i][n][0], a1=acc[i][n][1], a2=acc[i][n][2], a3=acc[i][n][3];
            s0 += a0 + a2; q0 = fmaf(a0,a0,fmaf(a2,a2,q0));
            s1 += a1 + a3; q1 = fmaf(a1,a1,fmaf(a3,a3,q1));
        }
        st[n][0]=s0; st[n][1]=q0; st[n][2]=s1; st[n][3]=q1;
    }
#pragma unroll
    for (int n = 0; n < NN; n++)
#pragma unroll
        for (int j = 0; j < 4; j++) {
            st[n][j] += __shfl_xor_sync(0xffffffffu, st[n][j], 4);
            st[n][j] += __shfl_xor_sync(0xffffffffu, st[n][j], 8);
            st[n][j] += __shfl_xor_sync(0xffffffffu, st[n][j], 16);
        }
    float* sred = (float*)dsm;
    __syncthreads();
    if (lane < 4) {
#pragma unroll
        for (int n = 0; n < NN; n++)
#pragma unroll
            for (int j = 0; j < 4; j++)
                sred[((w * NN + n) * 4 + t) * 4 + j] = st[n][j];
    }
    __syncthreads();
    if (tid < NN * 16) {
        int n = tid >> 4, tt = (tid >> 2) & 3, j = tid & 3;
        float s = 0.f;
#pragma unroll
        for (int ww = 0; ww < 8; ww++) s += sred[((ww * NN + n) * 4 + tt) * 4 + j];
        int c = n * 8 + 2 * tt + (j >> 1);
        g_part[(((size_t)b * nt + tile) * COUT + c) * 2 + (j & 1)] = s;
    }
}

// ---------------- mma.sync conv (convs 2-6), smem-B, fused stats -----------
template<int DIL, int MODE, int CIN, int CREAL, int COUT, int S, int XTILE, int POOL>
__global__ __launch_bounds__(256)
void conv_mma(const float* __restrict__ in, float* __restrict__ out, int imgOff) {
    constexpr int WB = 25 * COUT * 36;
    constexpr int NC = CIN / 16;
    constexpr int XP = XTILE + 4 * DIL;
    constexpr int R  = 4 + 4 * DIL;
    constexpr int PS0 = R * XP;
    constexpr int PSTRIDE = PS0 + ((40 - (PS0 & 31)) & 31);
    constexpr int T  = XTILE / 32;
    constexpr int NN = COUT / 8;
    constexpr int NXT = S / XTILE;
    extern __shared__ __align__(16) char dsm[];
    uint32_t* sStage = (uint32_t*)(dsm + WB);
    const int tid = threadIdx.x, w = tid >> 5, lane = tid & 31;
    const int g = lane >> 2, t = lane & 3;
    const int b = blockIdx.y;
    const int xt = blockIdx.x % NXT, yt = blockIdx.x / NXT;
    const int y0 = yt * 4, x0 = xt * XTILE;
    const int ry = w >> 1, xseg = (w & 1) * (XTILE / 2);
    float acc[T][NN][4];
#pragma unroll
    for (int i = 0; i < T; i++)
#pragma unroll
        for (int n = 0; n < NN; n++)
#pragma unroll
            for (int j = 0; j < 4; j++) acc[i][n][j] = 0.f;
    const unsigned char* img = g_wimg + (size_t)b * SAMP + imgOff;

#pragma unroll 1
    for (int chunk = 0; chunk < NC; chunk++) {
        __syncthreads();
        {
            const uint4* src = (const uint4*)(img + (size_t)chunk * WB);
            uint4* dst = (uint4*)dsm;
            for (int i = tid; i < WB / 16; i += 256) dst[i] = src[i];
        }
        {
            int cb = chunk * 16;
            for (int idx = tid; idx < 8 * PS0; idx += 256) {
                int p = idx / PS0, rem = idx - p * PS0;
                int r = rem / XP, xp = rem - r * XP;
                int iy = y0 + r - 2 * DIL, ix = x0 + xp - 2 * DIL;
                int c0 = cb + p * 2;
                float v0 = 0.f, v1 = 0.f;
                if (iy >= 0 && iy < S && ix >= 0 && ix < S && c0 < CREAL) {
                    const float* bp = in + ((size_t)(b * CREAL + c0)) * (S * S) + (size_t)iy * S + ix;
                    v0 = bp[0]; v1 = bp[(size_t)S * S];
                    if (MODE) {
                        v0 = fmaf(v0, g_stats[(b*CREAL+c0)*2],   g_stats[(b*CREAL+c0)*2+1]);
                        v1 = fmaf(v1, g_stats[(b*CREAL+c0+1)*2], g_stats[(b*CREAL+c0+1)*2+1]);
                        if (MODE == 2) { v0 = fmaxf(v0, 0.f); v1 = fmaxf(v1, 0.f); }
                    }
                }
                uint32_t hp = cvt2h(v1, v0);
                __half2 hh = *reinterpret_cast<__half2*>(&hp);
                float2 bk = __half22float2(hh);
                uint32_t lp = cvt2h(v1 - bk.y, v0 - bk.x);
                sStage[p * PSTRIDE + rem]       = hp;
                sStage[(8 + p) * PSTRIDE + rem] = lp;
            }
        }
        __syncthreads();
#pragma unroll 1
        for (int ky = 0; ky < 5; ky++) {
#pragma unroll 1
            for (int kx = 0; kx < 5; kx++) {
                int off = (ry + ky * DIL) * XP + xseg + kx * DIL + g;
                uint32_t ah[T][4], al[T][4];
#pragma unroll
                for (int i = 0; i < T; i++) {
                    int o = off + i * 16;
                    ah[i][0] = sStage[t * PSTRIDE + o];
                    ah[i][1] = sStage[t * PSTRIDE + o + 8];
                    ah[i][2] = sStage[(t + 4) * PSTRIDE + o];
                    ah[i][3] = sStage[(t + 4) * PSTRIDE + o + 8];
                    al[i][0] = sStage[(t + 8) * PSTRIDE + o];
                    al[i][1] = sStage[(t + 8) * PSTRIDE + o + 8];
                    al[i][2] = sStage[(t + 12) * PSTRIDE + o];
                    al[i][3] = sStage[(t + 12) * PSTRIDE + o + 8];
                }
                const char* wB = dsm + ((ky * 5 + kx) * COUT + g) * 36 + t * 4;
                uint32_t bb[NN][2];
#pragma unroll
                for (int n = 0; n < NN; n++) {
                    bb[n][0] = *(const uint32_t*)(wB + n * 288);
                    bb[n][1] = *(const uint32_t*)(wB + n * 288 + 16);
                }
#pragma unroll
                for (int n = 0; n < NN; n++)
#pragma unroll
                    for (int i = 0; i < T; i++)
                        mma16816(acc[i][n], ah[i][0], ah[i][1], ah[i][2], ah[i][3], bb[n][0], bb[n][1]);
#pragma unroll
                for (int n = 0; n < NN; n++)
#pragma unroll
                    for (int i = 0; i < T; i++)
                        mma16816(acc[i][n], al[i][0], al[i][1], al[i][2], al[i][3], bb[n][0], bb[n][1]);
            }
        }
    }
    if (!POOL) {
        int row = y0 + ry;
        float* orow = out + ((size_t)b * COUT) * (S * S) + (size_t)row * S;
#pragma unroll
        for (int i = 0; i < T; i++) {
            int px = x0 + xseg + i * 16 + g;
#pragma unroll
            for (int n = 0; n < NN; n++) {
                float* p0 = orow + ((size_t)(n * 8 + 2 * t)) * (S * S);
                float* p1 = p0 + (size_t)S * S;
                p0[px]     = acc[i][n][0];
                p1[px]     = acc[i][n][1];
                p0[px + 8] = acc[i][n][2];
                p1[px + 8] = acc[i][n][3];
            }
        }
    }
    stats_epilogue<T, NN, COUT>(acc, dsm, tid, w, lane, t, b, blockIdx.x, gridDim.x);
    if (POOL) {
        float* pbuf = (float*)(dsm + WB);
#pragma unroll
        for (int i = 0; i < T; i++) {
            int col = xseg + i * 16 + g;
#pragma unroll
            for (int n = 0; n < NN; n++) {
                int c0 = n * 8 + 2 * t;
                pbuf[c0 * (4 * XTILE) + ry * XTILE + col]           = acc[i][n][0];
                pbuf[(c0 + 1) * (4 * XTILE) + ry * XTILE + col]     = acc[i][n][1];
                pbuf[c0 * (4 * XTILE) + ry * XTILE + col + 8]       = acc[i][n][2];
                pbuf[(c0 + 1) * (4 * XTILE) + ry * XTILE + col + 8] = acc[i][n][3];
            }
        }
        __syncthreads();
        for (int k = tid; k < COUT * 2 * (XTILE / 2); k += 256) {
            int c = k / (2 * (XTILE / 2));
            int rem = k - c * 2 * (XTILE / 2);
            int pr = rem / (XTILE / 2), pc = rem - pr * (XTILE / 2);
            const float* pb = pbuf + c * (4 * XTILE);
            float v = 0.25f * (pb[(2*pr) * XTILE + 2*pc] + pb[(2*pr) * XTILE + 2*pc + 1]
                             + pb[(2*pr+1) * XTILE + 2*pc] + pb[(2*pr+1) * XTILE + 2*pc + 1]);
            out[((size_t)(b * COUT + c)) * ((S/2)*(S/2)) + (size_t)(y0/2 + pr) * (S/2) + (x0/2 + pc)] = v;
        }
    }
}

// ---------------- conv1: tap-paired k16, gmem-B fragments ------------------
__global__ __launch_bounds__(256)
void conv1_mma(const float* __restrict__ in, float* __restrict__ out, int imgOff) {
    constexpr int S = 256, XTILE = 128, XP = 136, PS0 = 12 * 136;
    constexpr int PSTRIDE = 1640, T = 4, NN = 2;
    extern __shared__ __align__(16) char dsm[];
    uint32_t* sStage = (uint32_t*)dsm;
    const int tid = threadIdx.x, w = tid >> 5, lane = tid & 31;
    const int g = lane >> 2, t = lane & 3;
    const int b = blockIdx.y;
    const int xt = blockIdx.x & 1, yt = blockIdx.x >> 1;
    const int y0 = yt * 4, x0 = xt * XTILE;
    const int ry = w >> 1, xseg = (w & 1) * 64;
    float acc[T][NN][4];
#pragma unroll
    for (int i = 0; i < T; i++)
#pragma unroll
        for (int n = 0; n < NN; n++)
#pragma unroll
            for (int j = 0; j < 4; j++) acc[i][n][j] = 0.f;
    const unsigned char* img = g_wimg + (size_t)b * SAMP + imgOff;
    {
        for (int idx = tid; idx < 4 * PS0; idx += 256) {
            int p = idx / PS0, rem = idx - p * PS0;
            int r = rem / XP, xp = rem - r * XP;
            int iy = y0 + r - 4, ix = x0 + xp - 4;
            int c0 = p * 2;
            float v0 = 0.f, v1 = 0.f;
            if (iy >= 0 && iy < S && ix >= 0 && ix < S) {
                const float* bp = in + ((size_t)(b * 8 + c0)) * 65536 + (size_t)iy * S + ix;
                v0 = bp[0]; v1 = bp[65536];
                v0 = fmaf(v0, g_stats[(b*8+c0)*2],   g_stats[(b*8+c0)*2+1]);
                v1 = fmaf(v1, g_stats[(b*8+c0+1)*2], g_stats[(b*8+c0+1)*2+1]);
            }
            uint32_t hp = cvt2h(v1, v0);
            __half2 hh = *reinterpret_cast<__half2*>(&hp);
            float2 bk = __half22float2(hh);
            uint32_t lp = cvt2h(v1 - bk.y, v0 - bk.x);
            sStage[p * PSTRIDE + rem]       = hp;
            sStage[(4 + p) * PSTRIDE + rem] = lp;
        }
    }
    __syncthreads();
#pragma unroll 1
    for (int q = 0; q < 13; q++) {
        int tap1 = 2 * q, tap2 = (2 * q + 1 < 25) ? 2 * q + 1 : 24;
        int ky1 = tap1 / 5, kx1 = tap1 - ky1 * 5;
        int ky2 = tap2 / 5, kx2 = tap2 - ky2 * 5;
        int o1 = (ry + ky1 * 2) * XP + xseg + kx1 * 2 + g;
        int o2 = (ry + ky2 * 2) * XP + xseg + kx2 * 2 + g;
        uint32_t ah[T][4], al[T][4];
#pragma unroll
        for (int i = 0; i < T; i++) {
            int p1 = o1 + i * 16, p2 = o2 + i * 16;
            ah[i][0] = sStage[t * PSTRIDE + p1];
            ah[i][1] = sStage[t * PSTRIDE + p1 + 8];
            ah[i][2] = sStage[t * PSTRIDE + p2];
            ah[i][3] = sStage[t * PSTRIDE + p2 + 8];
            al[i][0] = sStage[(t + 4) * PSTRIDE + p1];
            al[i][1] = sStage[(t + 4) * PSTRIDE + p1 + 8];
            al[i][2] = sStage[(t + 4) * PSTRIDE + p2];
            al[i][3] = sStage[(t + 4) * PSTRIDE + p2 + 8];
        }
        const uint4* wp = (const uint4*)(img + (size_t)(((q*8+g)*4+t) * 16));
        uint4 qv = *wp;
        uint32_t bb[NN][2];
        bb[0][0] = qv.x; bb[0][1] = qv.y; bb[1][0] = qv.z; bb[1][1] = qv.w;
#pragma unroll
        for (int n = 0; n < NN; n++)
#pragma unroll
            for (int i = 0; i < T; i++)
                mma16816(acc[i][n], ah[i][0], ah[i][1], ah[i][2], ah[i][3], bb[n][0], bb[n][1]);
#pragma unroll
        for (int n = 0; n < NN; n++)
#pragma unroll
            for (int i = 0; i < T; i++)
                mma16816(acc[i][n], al[i][0], al[i][1], al[i][2], al[i][3], bb[n][0], bb[n][1]);
    }
    int row = y0 + ry;
    float* orow = out + ((size_t)b * 16) * 65536 + (size_t)row * S;
#pragma unroll
    for (int i = 0; i < T; i++) {
        int px = x0 + xseg + i * 16 + g;
#pragma unroll
        for (int n = 0; n < NN; n++) {
            float* p0 = orow + ((size_t)(n * 8 + 2 * t)) * 65536;
            float* p1 = p0 + 65536;
            p0[px]     = acc[i][n][0];
            p1[px]     = acc[i][n][1];
            p0[px + 8] = acc[i][n][2];
            p1[px + 8] = acc[i][n][3];
        }
    }
    stats_epilogue<T, NN, 16>(acc, dsm, tid, w, lane, t, b, blockIdx.x, gridDim.x);
}

// ---------------- 1x1 conv / upsample+softmax ----------------
__global__ void conv1x1(const float* __restrict__ in, float* __restrict__ out) {
    __shared__ float sw[512];
    int b = blockIdx.y;
    const float* wb = g_y + (size_t)b * WTOT + 201600;
    for (int i = threadIdx.x; i < 512; i += blockDim.x) sw[i] = wb[i];
    __syncthreads();
    int pix = blockIdx.x * blockDim.x + threadIdx.x;
    if (pix >= 16384) return;
    float acc[8] = {0,0,0,0,0,0,0,0};
    for (int c = 0; c < 64; c++) {
        float v = in[((size_t)(b*64 + c)) * 16384 + pix];
        v = fmaf(v, g_stats[(b*64+c)*2], g_stats[(b*64+c)*2+1]);
#pragma unroll
        for (int o = 0; o < 8; o++) acc[o] = fmaf(v, sw[o*64 + c], acc[o]);
    }
#pragma unroll
    for (int o = 0; o < 8; o++) out[((size_t)(b*8 + o)) * 16384 + pix] = acc[o];
}

__global__ void up_softmax(const float* __restrict__ in, float* __restrict__ out) {
    int idx = blockIdx.x * blockDim.x + threadIdx.x;
    if (idx >= NB * 65536) return;
    int x = idx & 255, y = (idx >> 8) & 255, b = idx >> 16;
    const float r = 127.0f / 255.0f;
    float sy = y * r, sx = x * r;
    int y0 = (int)sy, x0 = (int)sx;
    int y1 = min(y0 + 1, 127), x1 = min(x0 + 1, 127);
    float wy = sy - (float)y0, wx = sx - (float)x0;
    const float* bp = in + (size_t)b * 8 * 16384;
    float v[8], m = -1e30f;
#pragma unroll
    for (int o = 0; o < 8; o++) {
        const float* p = bp + o * 16384;
        float a00 = p[y0*128+x0], a01 = p[y0*128+x1];
        float a10 = p[y1*128+x0], a11 = p[y1*128+x1];
        float t0 = a00 * (1.f - wy) + a10 * wy;
        float t1 = a01 * (1.f - wy) + a11 * wy;
        v[o] = t0 * (1.f - wx) + t1 * wx;
        m = fmaxf(m, v[o]);
    }
    float s = 0.f;
#pragma unroll
    for (int o = 0; o < 8; o++) { v[o] = expf(v[o] - m); s += v[o]; }
    float invs = 1.f / s;
    size_t base = ((size_t)b * 8) * 65536 + (size_t)y * 256 + x;
#pragma unroll
    for (int o = 0; o < 8; o++) out[base + (size_t)o * 65536] = v[o] * invs;
}

// ---------------------------------------------------------------------------
extern "C" void kernel_launch(void* const* d_in, const int* in_sizes, int n_in,
                              void* d_out, int out_size) {
    const float* x   = (const float*)d_in[0];
    const float* act = (const float*)d_in[1];
    const float* g[7]; const float* be[7];
    for (int i = 0; i < 7; i++) { g[i] = (const float*)d_in[16 + 2*i]; be[i] = (const float*)d_in[17 + 2*i]; }
    float* out = (float*)d_out;
    float *pA = nullptr, *pB = nullptr;
    cudaGetSymbolAddress((void**)&pA, g_A);
    cudaGetSymbolAddress((void**)&pB, g_B);

    const int SM1 = 8 * 1640 * 4;            //  52480 (stage only, gmem-B)
    const int SM2 = 14400 + 16 * 1064 * 4;   //  82496
    const int SM3 = 28800 + 16 * 872  * 4;   //  84608
    const int SM4 = 28800 + 16 * 552  * 4;   //  64128
    const int SM5 = 57600 + 16 * 872  * 4;   // 113408
    const int SM6 = 57600 + 16 * 552  * 4;   //  92928
    cudaFuncSetAttribute(conv1_mma, cudaFuncAttributeMaxDynamicSharedMemorySize, SM1);
    cudaFuncSetAttribute(conv_mma<1,2,16,16,16,256,128,1>, cudaFuncAttributeMaxDynamicSharedMemorySize, SM2);
    cudaFuncSetAttribute(conv_mma<2,1,16,16,32,128,64,0>,  cudaFuncAttributeMaxDynamicSharedMemorySize, SM3);
    cudaFuncSetAttribute(conv_mma<1,2,32,32,32,128,64,0>,  cudaFuncAttributeMaxDynamicSharedMemorySize, SM4);
    cudaFuncSetAttribute(conv_mma<2,1,32,32,64,128,64,0>,  cudaFuncAttributeMaxDynamicSharedMemorySize, SM5);
    cudaFuncSetAttribute(conv_mma<1,2,64,64,64,128,64,0>,  cudaFuncAttributeMaxDynamicSharedMemorySize, SM6);

    gen_all<<<(WTOT + 255) / 256, 256>>>(
        (const float*)d_in[2],  (const float*)d_in[3],
        (const float*)d_in[4],  (const float*)d_in[5],
        (const float*)d_in[6],  (const float*)d_in[7],
        (const float*)d_in[8],  (const float*)d_in[9],
        (const float*)d_in[10], (const float*)d_in[11],
        (const float*)d_in[12], (const float*)d_in[13],
        (const float*)d_in[14], (const float*)d_in[15], act);
    prep_all<<<dim3((226528 + 255) / 256, NB), 256>>>();

    bn_stats<<<NB * 8, 256>>>(x, g[0], be[0], 8, 65536);
    conv1_mma<<<dim3(128, NB), 256, SM1>>>(x, pA, 446400);
    bn_finalize<<<(NB*16 + 255)/256, 256>>>(g[1], be[1], 16, 128, 1.f/65536.f);
    conv_mma<1,2,16,16,16,256,128,1><<<dim3(128, NB), 256, SM2>>>(pA, pB, 432000);   // conv2 + pool
    bn_finalize<<<(NB*16 + 255)/256, 256>>>(g[2], be[2], 16, 128, 1.f/65536.f);
    conv_mma<2,1,16,16,32,128,64,0><<<dim3(64, NB), 256, SM3>>>(pB, pA, 0);          // conv3
    bn_finalize<<<(NB*32 + 255)/256, 256>>>(g[3], be[3], 32, 64, 1.f/16384.f);
    conv_mma<1,2,32,32,32,128,64,0><<<dim3(64, NB), 256, SM4>>>(pA, pB, 28800);      // conv4
    bn_finalize<<<(NB*32 + 255)/256, 256>>>(g[4], be[4], 32, 64, 1.f/16384.f);
    conv_mma<2,1,32,32,64,128,64,0><<<dim3(64, NB), 256, SM5>>>(pB, pA, 86400);      // conv5
    bn_finalize<<<(NB*64 + 255)/256, 256>>>(g[5], be[5], 64, 64, 1.f/16384.f);
    conv_mma<1,2,64,64,64,128,64,0><<<dim3(64, NB), 256, SM6>>>(pA, pB, 201600);     // conv6
    bn_finalize<<<(NB*64 + 255)/256, 256>>>(g[6], be[6], 64, 64, 1.f/16384.f);

    conv1x1<<<dim3(64, NB), 256>>>(pB, pA);
    up_softmax<<<(NB * 65536 + 255) / 256, 256>>>(pA, out);
}